// round 14
// baseline (speedup 1.0000x reference)
#include <cuda_runtime.h>
#include <cstdint>

// Problem sizes (fixed by reference)
#define S_DIM  1024
#define P_DIM  8
#define N_PTS  8192            // S*P flattened colors

// NOTE: the reference sorts palette rows per column before the softmin, but
// the final loss is a MEAN over all queries -> permutation-invariant. The
// sort is a no-op on the output scalar and is omitted entirely.

#define BLK    256             // 8 warps/block
#define GX     32              // query columns: 32 * 256 = 8192 queries
#define NCH    37              // key chunks; grid 32 x 37 = 1184 = 8 blocks/SM
                               // (register-light scalar body) -> 64 warps/SM
#define MC     222             // ceil(8192/37); last chunk = 200

// Coordinates pre-scaled by LG2E so u = sqrt(s') = log2(e)*dist and
// exp(-dist) = ex2(-u): zero extra FMA for the exponent argument.
#define LG2E  1.4426950408889634f
#define ILG2E 0.6931471805599453f

// Static device scratch (no allocations allowed)
__device__ float4 g_scratch[NCH * N_PTS];    // per-chunk partials {sum_w, accx, accy, accz}

__device__ __forceinline__ float sqrt_ap(float x) {
    float r; asm("sqrt.approx.f32 %0, %1;" : "=f"(r) : "f"(x)); return r;
}
__device__ __forceinline__ float ex2_ap(float x) {
    float r; asm("ex2.approx.f32 %0, %1;" : "=f"(r) : "f"(x)); return r;
}

// Clipped, LG2E-scaled palette color for query q.
__device__ __forceinline__ float4 query_quad(const float* __restrict__ pallet, int q) {
    float x = fminf(fmaxf(pallet[3 * q]     * 0.5f, 0.f), 1.f);
    float y = fminf(fmaxf(pallet[3 * q + 1] * 0.5f, 0.f), 1.f);
    float z = fminf(fmaxf(pallet[3 * q + 2] * 0.5f, 0.f), 1.f);
    float ax = x * LG2E, ay = y * LG2E, az = z * LG2E;
    return make_float4(ax, ay, az, ax * ax + ay * ay + az * az);
}

// ---------------------------------------------------------------------------
// Phase 1: 8192x8192 softmin sweep. SCALAR body (1 query/thread): per key
// 1 LDS.128 + 4 FMA (dot via norm trick) + 2 MUFU + 4 FMA-class acc.
// ~30 regs -> 8 blocks/SM co-resident (16 warps/SMSP) to bury the
// LDS->dot->sqrt->ex2 latency chain and MUFU backpressure bubbles.
// grid (32, 37), BLK=256; key chunk prepped inline.
// ---------------------------------------------------------------------------
__global__ void __launch_bounds__(BLK) softmin_kernel(const float* __restrict__ pallet,
                                                      const float* __restrict__ comp) {
    __shared__ float4 sb[MC];    // {|B|^2, -2Bx, -2By, -2Bz} per key

    const int m0 = blockIdx.y * MC;
    const int mc = min(MC, N_PTS - m0);
    if (threadIdx.x < mc) {
        const int m = m0 + threadIdx.x;
        float bx = comp[3 * m] * LG2E, by = comp[3 * m + 1] * LG2E, bz = comp[3 * m + 2] * LG2E;
        sb[threadIdx.x] = make_float4(bx * bx + by * by + bz * bz,
                                      -2.f * bx, -2.f * by, -2.f * bz);
    }

    const int q = blockIdx.x * BLK + threadIdx.x;
    const float4 a = query_quad(pallet, q);
    const float Ax = a.x, Ay = a.y, Az = a.z, A2 = a.w;
    float sw = 0.f, cx = 0.f, cy = 0.f, cz = 0.f;

    __syncthreads();

#pragma unroll 4
    for (int i = 0; i < mc; i++) {
        const float4 b = sb[i];
        // s' = |A|^2 + |B|^2 - 2 A.B  (= log2e^2 * |a-b|^2)
        float s = fmaf(b.y, Ax, fmaf(b.z, Ay, fmaf(b.w, Az, b.x + A2)));
        // u = log2e * dist; w = 2^(-u) = exp(-dist). |.| and neg fold into MUFU.
        float w = ex2_ap(-sqrt_ap(fabsf(s)));
        sw += w;
        cx = fmaf(w, b.y, cx);   // accumulates w*(-2*LG2E*bx) etc.
        cy = fmaf(w, b.z, cy);
        cz = fmaf(w, b.w, cz);
    }

    g_scratch[blockIdx.y * N_PTS + q] = make_float4(sw, cx, cy, cz);
}

// ---------------------------------------------------------------------------
// Phase 2: combine chunk partials (coalesced), MSE reduce. Round-13 config
// (measured 5.8us): 256 blocks x 512 threads, lanes = consecutive q,
// warps stride the 37 chunks.
// ---------------------------------------------------------------------------
#define RBLK 512
#define RWARPS (RBLK / 32)
__global__ void __launch_bounds__(RBLK) reduce_kernel(const float* __restrict__ pallet,
                                                      float* __restrict__ out) {
    const int lane = threadIdx.x & 31;
    const int wid  = threadIdx.x >> 5;            // 0..15
    const int q    = blockIdx.x * 32 + lane;

    float sw = 0.f, cx = 0.f, cy = 0.f, cz = 0.f;
#pragma unroll
    for (int ch = wid; ch < NCH; ch += RWARPS) {
        float4 v = g_scratch[ch * N_PTS + q];
        sw += v.x; cx += v.y; cy += v.z; cz += v.w;
    }

    __shared__ float4 part[RWARPS][32];
    part[wid][lane] = make_float4(sw, cx, cy, cz);
    __syncthreads();

    if (wid == 0) {
#pragma unroll
        for (int w = 1; w < RWARPS; w++) {
            float4 v = part[w][lane];
            sw += v.x; cx += v.y; cy += v.z; cz += v.w;
        }
        // closest_c = acc_c / (-2 * LG2E * sum_w)   (acc holds w * -2*LG2E*b)
        const float inv = -1.f / (2.f * LG2E * sw);
        float clx = cx * inv, cly = cy * inv, clz = cz * inv;

        float4 a = query_quad(pallet, q);          // LG2E-scaled
        float ex = a.x * ILG2E - clx;
        float ey = a.y * ILG2E - cly;
        float ez = a.z * ILG2E - clz;
        float local = ex * ex + ey * ey + ez * ez;

        for (int off = 16; off > 0; off >>= 1)
            local += __shfl_down_sync(0xFFFFFFFFu, local, off);
        if (lane == 0)
            atomicAdd(out, local * (1.f / (float)(N_PTS * 3)));
    }
}

// ---------------------------------------------------------------------------
extern "C" void kernel_launch(void* const* d_in, const int* in_sizes, int n_in,
                              void* d_out, int out_size) {
    const float* pallet = (const float*)d_in[0];
    const float* comp   = (const float*)d_in[1];
    float* out = (float*)d_out;

    cudaMemsetAsync(out, 0, sizeof(float));
    softmin_kernel<<<dim3(GX, NCH), BLK>>>(pallet, comp);
    reduce_kernel<<<N_PTS / 32, RBLK>>>(pallet, out);
}

// round 15
// speedup vs baseline: 1.1298x; 1.1298x over previous
#include <cuda_runtime.h>
#include <cuda_fp16.h>
#include <cstdint>

// Problem sizes (fixed by reference)
#define S_DIM  1024
#define P_DIM  8
#define N_PTS  8192            // S*P flattened colors

// NOTE: the reference sorts palette rows per column before the softmin, but
// the final loss is a MEAN over all queries -> permutation-invariant. The
// sort is a no-op on the output scalar and is omitted entirely.

#define Q_PER_THREAD 2         // 1 packed pair per thread
#define BLK          256       // 8 warps/block
#define NCH          37        // key chunks; grid 16 x 37 = 592 = 4 blocks/SM
#define MC           222       // ceil(8192/37); last chunk = 200 (both even)

// Coordinates pre-scaled by LG2E so u = sqrt(s') = log2(e)*dist and
// exp(-dist) = ex2(-u). Poly path: degree-5 minimax of exp(-u*ln2).
#define LG2E  1.4426950408889634f
#define ILG2E 0.6931471805599453f
#define P0    1.0000332f
#define P1   -0.6928500f
#define P2    0.2389700f
#define P3   -0.0533300f
#define P4    0.0078085f
#define P5   -0.0005782f

// Static device scratch: fp16-packed per-chunk partials
// {h2(sum_w, accx), h2(accy, accz)} -> 8 bytes/query/chunk (2.4MB total).
__device__ uint2 g_scratch[NCH * N_PTS];

// ---- packed f32x2 helpers -------------------------------------------------
union f2u { float2 f; unsigned long long u; };
__device__ __forceinline__ float2 ffma2(float2 a, float2 b, float2 c) {
    f2u A, B, C, D; A.f = a; B.f = b; C.f = c;
    asm("fma.rn.f32x2 %0, %1, %2, %3;" : "=l"(D.u) : "l"(A.u), "l"(B.u), "l"(C.u));
    return D.f;
}
__device__ __forceinline__ float2 fadd2(float2 a, float2 b) {
    f2u A, B, D; A.f = a; B.f = b;
    asm("add.rn.f32x2 %0, %1, %2;" : "=l"(D.u) : "l"(A.u), "l"(B.u));
    return D.f;
}
__device__ __forceinline__ float sqrt_ap(float x) {
    float r; asm("sqrt.approx.f32 %0, %1;" : "=f"(r) : "f"(x)); return r;
}
__device__ __forceinline__ float ex2_ap(float x) {
    float r; asm("ex2.approx.f32 %0, %1;" : "=f"(r) : "f"(x)); return r;
}
__device__ __forceinline__ unsigned int pack_h2(float a, float b) {
    __half2 h = __floats2half2_rn(a, b);
    return *reinterpret_cast<unsigned int*>(&h);
}
__device__ __forceinline__ float2 unpack_h2(unsigned int u) {
    __half2 h = *reinterpret_cast<__half2*>(&u);
    return __half22float2(h);
}

// Clipped, LG2E-scaled palette color for query q.
__device__ __forceinline__ float4 query_quad(const float* __restrict__ pallet, int q) {
    float x = fminf(fmaxf(pallet[3 * q]     * 0.5f, 0.f), 1.f);
    float y = fminf(fmaxf(pallet[3 * q + 1] * 0.5f, 0.f), 1.f);
    float z = fminf(fmaxf(pallet[3 * q + 2] * 0.5f, 0.f), 1.f);
    float ax = x * LG2E, ay = y * LG2E, az = z * LG2E;
    return make_float4(ax, ay, az, ax * ax + ay * ay + az * az);
}

// ---------------------------------------------------------------------------
// Phase 1: 8192x8192 softmin sweep — round-13 best config verbatim (keys
// alternate ex2/poly paths; grid (16,37), BLK=256, 2 packed queries/thread).
// Only the epilogue changed: fp16-packed scratch store, and one thread
// zero-inits out (replaces the memset node; runs before reduce by kernel order).
// ---------------------------------------------------------------------------
__global__ void __launch_bounds__(BLK, 4) softmin_kernel(const float* __restrict__ pallet,
                                                         const float* __restrict__ comp,
                                                         float* __restrict__ out) {
    // shared: lane-duplicated key quads: per i, {B2,B2,nx,nx} {ny,ny,nz,nz}
    __shared__ float4 sb[MC * 2];

    if (blockIdx.x == 0 && blockIdx.y == 0 && threadIdx.x == 0) out[0] = 0.f;

    const int m0 = blockIdx.y * MC;
    const int mc = min(MC, N_PTS - m0);
    if (threadIdx.x < mc) {
        const int m = m0 + threadIdx.x;
        float bx = comp[3 * m] * LG2E, by = comp[3 * m + 1] * LG2E, bz = comp[3 * m + 2] * LG2E;
        float b2 = bx * bx + by * by + bz * bz;
        float nx = -2.f * bx, ny = -2.f * by, nz = -2.f * bz;
        sb[2 * threadIdx.x]     = make_float4(b2, b2, nx, nx);
        sb[2 * threadIdx.x + 1] = make_float4(ny, ny, nz, nz);
    }

    const int q0 = blockIdx.x * (BLK * Q_PER_THREAD) + threadIdx.x * Q_PER_THREAD;
    float4 a0 = query_quad(pallet, q0);
    float4 a1 = query_quad(pallet, q0 + 1);
    const float2 Ax = make_float2(a0.x, a1.x);
    const float2 Ay = make_float2(a0.y, a1.y);
    const float2 Az = make_float2(a0.z, a1.z);
    const float2 A2 = make_float2(a0.w, a1.w);
    float2 sw = make_float2(0.f, 0.f), cx = sw, cy = sw, cz = sw;

    const float2 k0 = make_float2(P0, P0), k1 = make_float2(P1, P1),
                 k2 = make_float2(P2, P2), k3 = make_float2(P3, P3),
                 k4 = make_float2(P4, P4), k5 = make_float2(P5, P5);

    __syncthreads();

#pragma unroll 2
    for (int i = 0; i < mc; i += 2) {
        {   // --- key i: poly path (FP32-heavy) ---
            const float4 u4 = sb[2 * i], v4 = sb[2 * i + 1];
            const float2 B2 = make_float2(u4.x, u4.y);
            const float2 nx = make_float2(u4.z, u4.w);
            const float2 ny = make_float2(v4.x, v4.y);
            const float2 nz = make_float2(v4.z, v4.w);
            float2 sv = ffma2(nx, Ax, ffma2(ny, Ay, ffma2(nz, Az, fadd2(B2, A2))));
            float2 u = make_float2(sqrt_ap(fabsf(sv.x)), sqrt_ap(fabsf(sv.y)));
            float2 w = ffma2(k5, u, k4);              // Horner in u = LG2E*dist
            w = ffma2(w, u, k3);
            w = ffma2(w, u, k2);
            w = ffma2(w, u, k1);
            w = ffma2(w, u, k0);                      // ~= exp(-dist)
            sw = fadd2(sw, w);
            cx = ffma2(w, nx, cx);
            cy = ffma2(w, ny, cy);
            cz = ffma2(w, nz, cz);
        }
        {   // --- key i+1: ex2 path (MUFU-heavy) ---
            const float4 u4 = sb[2 * i + 2], v4 = sb[2 * i + 3];
            const float2 B2 = make_float2(u4.x, u4.y);
            const float2 nx = make_float2(u4.z, u4.w);
            const float2 ny = make_float2(v4.x, v4.y);
            const float2 nz = make_float2(v4.z, v4.w);
            float2 sv = ffma2(nx, Ax, ffma2(ny, Ay, ffma2(nz, Az, fadd2(B2, A2))));
            float2 w = make_float2(ex2_ap(-sqrt_ap(fabsf(sv.x))),
                                   ex2_ap(-sqrt_ap(fabsf(sv.y))));
            sw = fadd2(sw, w);
            cx = ffma2(w, nx, cx);
            cy = ffma2(w, ny, cy);
            cz = ffma2(w, nz, cz);
        }
    }

    uint2* dst = g_scratch + blockIdx.y * N_PTS + q0;
    dst[0] = make_uint2(pack_h2(sw.x, cx.x), pack_h2(cy.x, cz.x));
    dst[1] = make_uint2(pack_h2(sw.y, cx.y), pack_h2(cy.y, cz.y));
}

// ---------------------------------------------------------------------------
// Phase 2: combine fp16 chunk partials (coalesced, half the traffic of r13),
// MSE reduce. 256 blocks x 512 threads, lanes = consecutive q, warps stride
// the 37 chunks. Accumulation in fp32.
// ---------------------------------------------------------------------------
#define RBLK 512
#define RWARPS (RBLK / 32)
__global__ void __launch_bounds__(RBLK) reduce_kernel(const float* __restrict__ pallet,
                                                      float* __restrict__ out) {
    const int lane = threadIdx.x & 31;
    const int wid  = threadIdx.x >> 5;            // 0..15
    const int q    = blockIdx.x * 32 + lane;

    float sw = 0.f, cx = 0.f, cy = 0.f, cz = 0.f;
#pragma unroll
    for (int ch = wid; ch < NCH; ch += RWARPS) {
        uint2 v = g_scratch[ch * N_PTS + q];
        float2 p0 = unpack_h2(v.x);   // {sw, cx}
        float2 p1 = unpack_h2(v.y);   // {cy, cz}
        sw += p0.x; cx += p0.y; cy += p1.x; cz += p1.y;
    }

    __shared__ float4 part[RWARPS][32];
    part[wid][lane] = make_float4(sw, cx, cy, cz);
    __syncthreads();

    if (wid == 0) {
#pragma unroll
        for (int w = 1; w < RWARPS; w++) {
            float4 v = part[w][lane];
            sw += v.x; cx += v.y; cy += v.z; cz += v.w;
        }
        // closest_c = acc_c / (-2 * LG2E * sum_w)   (acc holds w * -2*LG2E*b)
        const float inv = -1.f / (2.f * LG2E * sw);
        float clx = cx * inv, cly = cy * inv, clz = cz * inv;

        float4 a = query_quad(pallet, q);          // LG2E-scaled
        float ex = a.x * ILG2E - clx;
        float ey = a.y * ILG2E - cly;
        float ez = a.z * ILG2E - clz;
        float local = ex * ex + ey * ey + ez * ez;

        for (int off = 16; off > 0; off >>= 1)
            local += __shfl_down_sync(0xFFFFFFFFu, local, off);
        if (lane == 0)
            atomicAdd(out, local * (1.f / (float)(N_PTS * 3)));
    }
}

// ---------------------------------------------------------------------------
extern "C" void kernel_launch(void* const* d_in, const int* in_sizes, int n_in,
                              void* d_out, int out_size) {
    const float* pallet = (const float*)d_in[0];
    const float* comp   = (const float*)d_in[1];
    float* out = (float*)d_out;

    softmin_kernel<<<dim3(N_PTS / (BLK * Q_PER_THREAD), NCH), BLK>>>(pallet, comp, out);
    reduce_kernel<<<N_PTS / 32, RBLK>>>(pallet, out);
}